// round 11
// baseline (speedup 1.0000x reference)
#include <cuda_runtime.h>
#include <cuda_fp16.h>
#include <cstdint>
#include <math.h>

#define BATCH 128
#define TT    127
#define SS    128
#define DIN   48
#define DKD   128
#define HH    8
#define LL    6
#define PP    8128
#define LHN   48
#define BS    (BATCH*SS)     /* 16384 */
#define BSD   (BS*DKD)       /* 2097152 */

typedef __half fp16;

// ---------------- scratch ----------------------------------------------------
__device__ float g_h[BSD];
__device__ float g_nrm[BS];
__device__ float g_cosv[LHN*PP];
__device__ float g_sinv[LHN*PP];
__device__ fp16  g_uhi[BSD];
__device__ fp16  g_Wthi[LHN*DKD*DKD];
__device__ fp16  g_Vwhi[LHN*DKD*DKD];
__device__ float g_hs[(size_t)HH*BSD];

// ---------------- helpers -----------------------------------------------------
__device__ __forceinline__ uint32_t smem_u32(const void* p) {
    uint32_t a;
    asm("{ .reg .u64 t; cvta.to.shared.u64 t, %1; cvt.u32.u64 %0, t; }" : "=r"(a) : "l"(p));
    return a;
}
__device__ __forceinline__ uint32_t pack2h(float x, float y)
{
    __half2 H = __halves2half2(__float2half_rn(x), __float2half_rn(y));
    return *reinterpret_cast<uint32_t*>(&H);
}
__device__ __forceinline__ void ldmx4(uint32_t* r, uint32_t addr)
{
    asm volatile("ldmatrix.sync.aligned.m8n8.x4.shared.b16 {%0,%1,%2,%3}, [%4];"
        : "=r"(r[0]), "=r"(r[1]), "=r"(r[2]), "=r"(r[3]) : "r"(addr));
}
__device__ __forceinline__ void mma16816(float* d, const uint32_t* a, const uint32_t* b)
{
    asm volatile("mma.sync.aligned.m16n8k16.row.col.f32.f16.f16.f32 "
        "{%0,%1,%2,%3}, {%4,%5,%6,%7}, {%8,%9}, {%0,%1,%2,%3};"
        : "+f"(d[0]), "+f"(d[1]), "+f"(d[2]), "+f"(d[3])
        : "r"(a[0]), "r"(a[1]), "r"(a[2]), "r"(a[3]), "r"(b[0]), "r"(b[1]));
}
#define CP16(dst, src) \
    asm volatile("cp.async.cg.shared.global [%0], [%1], 16;" :: "r"(dst), "l"(src))
#define CP_COMMIT() asm volatile("cp.async.commit_group;" ::: "memory")
#define CP_WAIT0()  asm volatile("cp.async.wait_group 0;" ::: "memory")
#define CP_WAIT1()  asm volatile("cp.async.wait_group 1;" ::: "memory")

// ---------------- embed + class token + LN0 ---------------------------------
__global__ void k_embed(const float* __restrict__ x, const float* __restrict__ ew,
                        const float* __restrict__ eb, const float* __restrict__ ct,
                        const float* __restrict__ g0, const float* __restrict__ b0)
{
    int bx = blockIdx.x;
    int b = bx >> 7, s = bx & 127;
    int d = threadIdx.x;
    __shared__ float xs[DIN];
    __shared__ float red[8];
    float v;
    if (s == 0) {
        v = ct[d];
    } else {
        if (d < DIN) xs[d] = x[(b*TT + (s-1))*DIN + d];
        __syncthreads();
        float acc = eb[d];
        const float* wrow = ew + d*DIN;
#pragma unroll
        for (int f = 0; f < DIN; f++) acc += xs[f]*wrow[f];
        v = acc;
    }
    float sum = v, sq = v*v;
#pragma unroll
    for (int o = 16; o; o >>= 1) {
        sum += __shfl_xor_sync(0xffffffffu, sum, o);
        sq  += __shfl_xor_sync(0xffffffffu, sq,  o);
    }
    if ((d & 31) == 0) { red[d>>5] = sum; red[4 + (d>>5)] = sq; }
    __syncthreads();
    float ts = red[0]+red[1]+red[2]+red[3];
    float tq = red[4]+red[5]+red[6]+red[7];
    float mean = ts * (1.0f/DKD);
    float var  = tq * (1.0f/DKD) - mean*mean;
    float inv  = rsqrtf(var + 1e-5f);
    g_h[(size_t)bx*DKD + d] = (v - mean)*inv*g0[d] + b0[d];
}

// ---------------- sincos precompute ------------------------------------------
__global__ void k_cs(const float* __restrict__ phi)
{
    int i = blockIdx.x*blockDim.x + threadIdx.x;
    if (i < LHN*PP) {
        float s, c;
        sincosf(phi[i], &s, &c);
        g_cosv[i] = c; g_sinv[i] = s;
    }
}

// ---------------- convert Vw (hi only) ----------------------------------------
__global__ void k_cvtVw(const float* __restrict__ Vw)
{
    int i = blockIdx.x*blockDim.x + threadIdx.x;
    if (i < LHN*DKD*DKD) g_Vwhi[i] = __float2half_rn(Vw[i]);
}

// ---------------- W build: brick-wall Givens pyramid -> transposed hi ---------
__global__ __launch_bounds__(256) void k_wbuild()
{
    int lh = blockIdx.x, cg = blockIdx.y;      // 48 x 4
    __shared__ float Wsh[SS][33];
    int tid = threadIdx.x;
    int col = tid & 31, slot = tid >> 5;
    for (int idx = tid; idx < SS*32; idx += 256) {
        int r = idx >> 5, c = idx & 31;
        Wsh[r][c] = (r == cg*32 + c) ? 1.0f : 0.0f;
    }
    __syncthreads();
    const float* cb = g_cosv + lh*PP;
    const float* sb = g_sinv + lh*PP;
    for (int t = 0; t <= 2*(SS-2); t++) {
        int par  = t & 1;
        int imax = min(t, 2*(SS-2) - t);
        int cnt  = ((imax - par) >> 1) + 1;
        for (int r = slot; r < cnt; r += 8) {
            int i = par + 2*r;
            int k = (t + i) >> 1;
            int p = ((k*(k+1)) >> 1) + k - i;
            float c = cb[p], s = sb[p];
            float ra = Wsh[i][col], rb = Wsh[i+1][col];
            Wsh[i][col]   = c*ra - s*rb;
            Wsh[i+1][col] = s*ra + c*rb;
        }
        __syncthreads();
    }
    for (int idx = tid; idx < 32*SS; idx += 256) {
        int r = idx & 127, c = idx >> 7;
        size_t o = (size_t)lh*DKD*DKD + (size_t)(cg*32 + c)*DKD + r;
        g_Wthi[o] = __float2half_rn(Wsh[r][c]);
    }
}

// ---------------- token norms + u hi (layer-0 prep) ---------------------------
__global__ void k_norm()
{
    int row = blockIdx.x;
    int d = threadIdx.x;
    float v = g_h[(size_t)row*DKD + d];
    float sq = v*v;
#pragma unroll
    for (int o = 16; o; o >>= 1) sq += __shfl_xor_sync(0xffffffffu, sq, o);
    __shared__ float red[4];
    if ((d & 31) == 0) red[d>>5] = sq;
    __syncthreads();
    float nrm = sqrtf(red[0]+red[1]+red[2]+red[3]);
    size_t o = (size_t)row*DKD + d;
    g_uhi[o] = __float2half_rn(v / nrm);
    if (d == 0) g_nrm[row] = nrm;
}

// ---------------- merge heads + norms + u hi (between layers) -----------------
__global__ void k_mergenorm(const float* __restrict__ mb, int l)
{
    int row = blockIdx.x;
    int d = threadIdx.x;
    size_t o = (size_t)row*DKD + d;
    float a = mb[l];
#pragma unroll
    for (int h = 0; h < HH; h++) a += g_hs[(size_t)h*BSD + o];
    float sq = a*a;
#pragma unroll
    for (int of = 16; of; of >>= 1) sq += __shfl_xor_sync(0xffffffffu, sq, of);
    __shared__ float red[4];
    if ((d & 31) == 0) red[d>>5] = sq;
    __syncthreads();
    float nrm = sqrtf(red[0]+red[1]+red[2]+red[3]);
    g_h[o] = a;
    g_uhi[o] = __float2half_rn(a / nrm);
    if (d == 0) g_nrm[row] = nrm;
}

// ---------------- fused layer kernel ------------------------------------------
#define TSTRIDE 136
#define TILE1   (128*TSTRIDE*2)        /* 34816 bytes, one fp16 tile */
#define RAO     0                      /* u   (persistent thru GEMM3) */
#define RBO     TILE1                  /* T1 -> P                     */
#define RCO     (2*TILE1)              /* W -> V^T                    */
#define RDO     (3*TILE1)              /* Vw                          */
#define SMO_F   (4*TILE1)
#define SMEM_TOTAL (4*TILE1 + 6144)

__device__ __forceinline__ void load_hi_async(uint32_t dst,
    const fp16* __restrict__ hi, int tid)
{
#pragma unroll
    for (int it = 0; it < 4; it++) {
        int idx = it*256 + tid;
        int row = idx >> 3, chunk = idx & 7;
        CP16(dst + (row*TSTRIDE + chunk*16)*2, hi + row*DKD + chunk*16);
        CP16(dst + (row*TSTRIDE + chunk*16 + 8)*2, hi + row*DKD + chunk*16 + 8);
    }
}

// 1-term fp16 128x128x128 gemm (A hi, B hi)
__device__ __forceinline__ void gemm1t(uint32_t aBase, uint32_t bBase,
                                       float acc[4][4][4], int lane, int wm, int wn)
{
    uint32_t aoff[4], b4off[2];
#pragma unroll
    for (int mi = 0; mi < 4; mi++)
        aoff[mi] = aBase + ((wm*64 + mi*16 + (lane & 15))*TSTRIDE + (lane >> 4)*8) * 2;
#pragma unroll
    for (int njp = 0; njp < 2; njp++)
        b4off[njp] = bBase + ((wn*32 + njp*16 + ((lane>>4)*8) + (lane & 7))*TSTRIDE
                              + (((lane >> 3) & 1)*8)) * 2;
#pragma unroll
    for (int mi = 0; mi < 4; mi++)
#pragma unroll
        for (int nj = 0; nj < 4; nj++)
#pragma unroll
            for (int q = 0; q < 4; q++) acc[mi][nj][q] = 0.0f;

#pragma unroll 2
    for (int kk = 0; kk < 8; kk++) {
        uint32_t k2 = kk*32;
        uint32_t ah[4][4], bh[2][4];
#pragma unroll
        for (int mi = 0; mi < 4; mi++)
            ldmx4(ah[mi], aoff[mi] + k2);
#pragma unroll
        for (int njp = 0; njp < 2; njp++)
            ldmx4(bh[njp], b4off[njp] + k2);
#pragma unroll
        for (int mi = 0; mi < 4; mi++)
#pragma unroll
            for (int nj = 0; nj < 4; nj++)
                mma16816(acc[mi][nj], ah[mi], &bh[nj>>1][(nj&1)*2]);
    }
}

// accumulator fragments -> smem fp16 hi tile (row-major A layout)
__device__ __forceinline__ void fragToTile(char* sm, uint32_t rOff, float acc[4][4][4],
                                           int lane, int wm, int wn)
{
    int gid = lane >> 2, tig = lane & 3;
#pragma unroll
    for (int mi = 0; mi < 4; mi++) {
        int r0 = wm*64 + mi*16 + gid;
#pragma unroll
        for (int nj = 0; nj < 4; nj++) {
            int c0 = wn*32 + nj*8 + tig*2;
#pragma unroll
            for (int half = 0; half < 2; half++) {
                int r = r0 + half*8;
                *(uint32_t*)(sm + rOff + (r*TSTRIDE + c0)*2) =
                    pack2h(acc[mi][nj][half*2], acc[mi][nj][half*2+1]);
            }
        }
    }
}

__global__ void __launch_bounds__(256, 1) k_layer(int l,
    const float* __restrict__ Vb, const float* __restrict__ lng,
    const float* __restrict__ lnb, const float* __restrict__ mw)
{
    extern __shared__ char sm[];
    uint32_t smb = smem_u32(sm);

    int bx = blockIdx.x;                 // batch / m-tile
    int h  = blockIdx.y;
    int tid = threadIdx.x, lane = tid & 31, wid = tid >> 5;
    int wm = wid >> 2, wn = wid & 3;
    int gid = lane >> 2, tig = lane & 3;

    float* fnrm = (float*)(sm + SMO_F);
    float* fvb  = fnrm + 128;
    float* fg   = fnrm + 256;
    float* fb   = fnrm + 384;
    float* red1 = fnrm + 512;            // 512 floats
    float* red2 = fnrm + 1024;           // 512 floats

    size_t tokBase = (size_t)bx*128*DKD;
    size_t lhOff   = (size_t)(l*HH + h)*DKD*DKD;
    size_t hsBase  = (size_t)h*BSD + tokBase;

    // group0: u -> RA, W -> RC ; group1: Vw -> RD
    load_hi_async(smb + RAO, g_uhi + tokBase, tid);
    load_hi_async(smb + RCO, g_Wthi + lhOff, tid);
    CP_COMMIT();
    load_hi_async(smb + RDO, g_Vwhi + lhOff, tid);
    CP_COMMIT();
    if (tid < 128) {
        fnrm[tid] = g_nrm[bx*128 + tid];
        fvb[tid]  = Vb[(l*HH+h)*DKD + tid];
        fg[tid]   = lng[(size_t)(l*HH+h)*DKD + tid];
        fb[tid]   = lnb[(size_t)(l*HH+h)*DKD + tid];
    }
    CP_WAIT1();                            // u + W landed
    __syncthreads();                       // S1

    float acc[4][4][4];

    // GEMM1: T1 = u @ W
    gemm1t(smb + RAO, smb + RCO, acc, lane, wm, wn);
    fragToTile(sm, RBO, acc, lane, wm, wn);
    __syncthreads();                       // S2: T1 visible, RC free

    // GEMM2: M = T1 @ u^T
    gemm1t(smb + RBO, smb + RAO, acc, lane, wm, wn);
    CP_WAIT0();                            // Vw landed
    __syncthreads();                       // S3: RB free; Vw visible

    // ---- register softmax (A = M^2*n*n*scale >= 0, no max pass) ----
    {
        const float scale = 0.08838834764831845f;    // 1/sqrt(128)
        float nc[8];
#pragma unroll
        for (int nj = 0; nj < 4; nj++) {
            int c0 = wn*32 + nj*8 + tig*2;
            nc[2*nj]   = fnrm[c0];
            nc[2*nj+1] = fnrm[c0+1];
        }
#pragma unroll
        for (int mi = 0; mi < 4; mi++)
#pragma unroll
        for (int half = 0; half < 2; half++) {
            int r = wm*64 + mi*16 + half*8 + gid;
            float nr = fnrm[r] * scale;
            float s = 0.0f;
#pragma unroll
            for (int nj = 0; nj < 4; nj++) {
                float m0 = acc[mi][nj][half*2], m1 = acc[mi][nj][half*2+1];
                float e0 = __expf(m0*m0 * nr * nc[2*nj]);
                float e1 = __expf(m1*m1 * nr * nc[2*nj+1]);
                acc[mi][nj][half*2]   = e0;
                acc[mi][nj][half*2+1] = e1;
                s += e0 + e1;
            }
            s += __shfl_xor_sync(0xffffffffu, s, 1);
            s += __shfl_xor_sync(0xffffffffu, s, 2);
            if (tig == 0) red1[r*4 + wn] = s;
        }
        __syncthreads();                   // S4: row partial sums
#pragma unroll
        for (int mi = 0; mi < 4; mi++)
#pragma unroll
        for (int half = 0; half < 2; half++) {
            int r = wm*64 + mi*16 + half*8 + gid;
            float inv = 1.0f / (red1[r*4] + red1[r*4+1] + red1[r*4+2] + red1[r*4+3]);
#pragma unroll
            for (int nj = 0; nj < 4; nj++) {
                int c0 = wn*32 + nj*8 + tig*2;
                *(uint32_t*)(sm + RBO + (r*TSTRIDE + c0)*2) =
                    pack2h(acc[mi][nj][half*2]*inv, acc[mi][nj][half*2+1]*inv);
            }
        }
    }

    // GEMM3: V' = u @ Vw^T ; V = nrm[t]*V' + vb[e]
    gemm1t(smb + RAO, smb + RDO, acc, lane, wm, wn);

    // V^T -> RC, scale by nrm, add bias
#pragma unroll
    for (int mi = 0; mi < 4; mi++) {
        int s0 = wm*64 + mi*16 + gid;
#pragma unroll
        for (int nj = 0; nj < 4; nj++) {
            int e0 = wn*32 + nj*8 + tig*2;
            float vb0 = fvb[e0], vb1 = fvb[e0+1];
#pragma unroll
            for (int half = 0; half < 2; half++) {
                int ss = s0 + half*8;
                float ns = fnrm[ss];
                *(fp16*)(sm + RCO + (e0*TSTRIDE + ss)*2)     = __float2half_rn(acc[mi][nj][half*2]*ns   + vb0);
                *(fp16*)(sm + RCO + ((e0+1)*TSTRIDE + ss)*2) = __float2half_rn(acc[mi][nj][half*2+1]*ns + vb1);
            }
        }
    }
    __syncthreads();                       // S5: P (RB) + V^T (RC) staged

    // GEMM4: O = P @ V^T
    gemm1t(smb + RBO, smb + RCO, acc, lane, wm, wn);

    // ---- register epilogue: +residual, LN (E[x^2]-m^2), *mw -> g_hs ----
    {
        float gg[8], bb[8];
#pragma unroll
        for (int nj = 0; nj < 4; nj++) {
            int c0 = wn*32 + nj*8 + tig*2;
            gg[2*nj] = fg[c0]; gg[2*nj+1] = fg[c0+1];
            bb[2*nj] = fb[c0]; bb[2*nj+1] = fb[c0+1];
        }
        float mwv = __ldg(mw + l*HH + h);
#pragma unroll
        for (int mi = 0; mi < 4; mi++)
#pragma unroll
        for (int half = 0; half < 2; half++) {
            int r = wm*64 + mi*16 + half*8 + gid;
            const float* hr = g_h + tokBase + (size_t)r*DKD;
            float s = 0.0f, s2 = 0.0f;
#pragma unroll
            for (int nj = 0; nj < 4; nj++) {
                int c0 = wn*32 + nj*8 + tig*2;
                float2 rv = *(const float2*)(hr + c0);
                float v0 = acc[mi][nj][half*2]   + rv.x;
                float v1 = acc[mi][nj][half*2+1] + rv.y;
                acc[mi][nj][half*2]   = v0;
                acc[mi][nj][half*2+1] = v1;
                s  += v0 + v1;
                s2 += v0*v0 + v1*v1;
            }
            s  += __shfl_xor_sync(0xffffffffu, s, 1);
            s  += __shfl_xor_sync(0xffffffffu, s, 2);
            s2 += __shfl_xor_sync(0xffffffffu, s2, 1);
            s2 += __shfl_xor_sync(0xffffffffu, s2, 2);
            if (tig == 0) { red1[r*4 + wn] = s; red2[r*4 + wn] = s2; }
        }
        __syncthreads();                   // S6
#pragma unroll
        for (int mi = 0; mi < 4; mi++)
#pragma unroll
        for (int half = 0; half < 2; half++) {
            int r = wm*64 + mi*16 + half*8 + gid;
            float s  = red1[r*4] + red1[r*4+1] + red1[r*4+2] + red1[r*4+3];
            float s2 = red2[r*4] + red2[r*4+1] + red2[r*4+2] + red2[r*4+3];
            float mean = s * (1.0f/DKD);
            float var  = s2 * (1.0f/DKD) - mean*mean;
            float inv  = rsqrtf(var + 1e-5f);
            float* op = g_hs + hsBase + (size_t)r*DKD;
#pragma unroll
            for (int nj = 0; nj < 4; nj++) {
                int c0 = wn*32 + nj*8 + tig*2;
                float2 o;
                o.x = ((acc[mi][nj][half*2]  -mean)*inv*gg[2*nj]   + bb[2*nj]  ) * mwv;
                o.y = ((acc[mi][nj][half*2+1]-mean)*inv*gg[2*nj+1] + bb[2*nj+1]) * mwv;
                *(float2*)(op + c0) = o;
            }
        }
    }
}

// ---------------- extract last token ------------------------------------------
__global__ void k_extract(float* __restrict__ out)
{
    int i = blockIdx.x*blockDim.x + threadIdx.x;
    if (i < BATCH*DKD) {
        int b = i >> 7, d = i & 127;
        out[i] = g_h[((size_t)b*SS + (SS-1))*DKD + d];
    }
}

// ---------------- launch ------------------------------------------------------
extern "C" void kernel_launch(void* const* d_in, const int* in_sizes, int n_in,
                              void* d_out, int out_size)
{
    const float* x        = (const float*)d_in[0];
    const float* embed_w  = (const float*)d_in[1];
    const float* embed_b  = (const float*)d_in[2];
    const float* class_tk = (const float*)d_in[3];
    const float* norm0_g  = (const float*)d_in[4];
    const float* norm0_b  = (const float*)d_in[5];
    const float* Vw       = (const float*)d_in[6];
    const float* Vb       = (const float*)d_in[7];
    const float* ln_g     = (const float*)d_in[8];
    const float* ln_b     = (const float*)d_in[9];
    const float* phi      = (const float*)d_in[10];
    const float* merger_w = (const float*)d_in[11];
    const float* merger_b = (const float*)d_in[12];
    float* out = (float*)d_out;

    static int smem_set = 0;
    if (!smem_set) {
        cudaFuncSetAttribute(k_layer, cudaFuncAttributeMaxDynamicSharedMemorySize, SMEM_TOTAL);
        smem_set = 1;
    }

    k_embed<<<BS, 128>>>(x, embed_w, embed_b, class_tk, norm0_g, norm0_b);
    k_cs<<<(LHN*PP + 255)/256, 256>>>(phi);
    k_wbuild<<<dim3(LHN, 4), 256>>>();
    k_cvtVw<<<(LHN*DKD*DKD + 255)/256, 256>>>(Vw);
    k_norm<<<BS, 128>>>();

    dim3 gg(BATCH, HH);
    for (int l = 0; l < LL; l++) {
        k_layer<<<gg, 256, SMEM_TOTAL>>>(l, Vb, ln_g, ln_b, merger_w);
        k_mergenorm<<<BS, 128>>>(merger_b, l);
    }
    k_extract<<<(BATCH*DKD + 255)/256, 256>>>(out);
}

// round 12
// speedup vs baseline: 1.7183x; 1.7183x over previous
#include <cuda_runtime.h>
#include <cuda_fp16.h>
#include <cstdint>
#include <math.h>

#define BATCH 128
#define TT    127
#define SS    128
#define DIN   48
#define DKD   128
#define HH    8
#define LL    6
#define PP    8128
#define LHN   48
#define BS    (BATCH*SS)     /* 16384 */
#define BSD   (BS*DKD)       /* 2097152 */

typedef __half fp16;

// ---------------- scratch ----------------------------------------------------
__device__ float g_h[BSD];
__device__ float g_nrm[BS];
__device__ float g_cosv[LHN*PP];
__device__ float g_sinv[LHN*PP];
__device__ fp16  g_uhi[BSD];
__device__ fp16  g_Wthi[LHN*DKD*DKD];
__device__ fp16  g_Vwhi[LHN*DKD*DKD];
__device__ float g_hs[(size_t)HH*BSD];

// ---------------- helpers -----------------------------------------------------
__device__ __forceinline__ uint32_t smem_u32(const void* p) {
    uint32_t a;
    asm("{ .reg .u64 t; cvta.to.shared.u64 t, %1; cvt.u32.u64 %0, t; }" : "=r"(a) : "l"(p));
    return a;
}
__device__ __forceinline__ uint32_t pack2h(float x, float y)
{
    __half2 H = __halves2half2(__float2half_rn(x), __float2half_rn(y));
    return *reinterpret_cast<uint32_t*>(&H);
}
__device__ __forceinline__ void ldmx4(uint32_t* r, uint32_t addr)
{
    asm volatile("ldmatrix.sync.aligned.m8n8.x4.shared.b16 {%0,%1,%2,%3}, [%4];"
        : "=r"(r[0]), "=r"(r[1]), "=r"(r[2]), "=r"(r[3]) : "r"(addr));
}
__device__ __forceinline__ void mma16816(float* d, const uint32_t* a, const uint32_t* b)
{
    asm volatile("mma.sync.aligned.m16n8k16.row.col.f32.f16.f16.f32 "
        "{%0,%1,%2,%3}, {%4,%5,%6,%7}, {%8,%9}, {%0,%1,%2,%3};"
        : "+f"(d[0]), "+f"(d[1]), "+f"(d[2]), "+f"(d[3])
        : "r"(a[0]), "r"(a[1]), "r"(a[2]), "r"(a[3]), "r"(b[0]), "r"(b[1]));
}
#define CP16(dst, src) \
    asm volatile("cp.async.cg.shared.global [%0], [%1], 16;" :: "r"(dst), "l"(src))
#define CP_COMMIT() asm volatile("cp.async.commit_group;" ::: "memory")
#define CP_WAIT0()  asm volatile("cp.async.wait_group 0;" ::: "memory")

// ---------------- embed + class token + LN0 ---------------------------------
__global__ void k_embed(const float* __restrict__ x, const float* __restrict__ ew,
                        const float* __restrict__ eb, const float* __restrict__ ct,
                        const float* __restrict__ g0, const float* __restrict__ b0)
{
    int bx = blockIdx.x;
    int b = bx >> 7, s = bx & 127;
    int d = threadIdx.x;
    __shared__ float xs[DIN];
    __shared__ float red[8];
    float v;
    if (s == 0) {
        v = ct[d];
    } else {
        if (d < DIN) xs[d] = x[(b*TT + (s-1))*DIN + d];
        __syncthreads();
        float acc = eb[d];
        const float* wrow = ew + d*DIN;
#pragma unroll
        for (int f = 0; f < DIN; f++) acc += xs[f]*wrow[f];
        v = acc;
    }
    float sum = v, sq = v*v;
#pragma unroll
    for (int o = 16; o; o >>= 1) {
        sum += __shfl_xor_sync(0xffffffffu, sum, o);
        sq  += __shfl_xor_sync(0xffffffffu, sq,  o);
    }
    if ((d & 31) == 0) { red[d>>5] = sum; red[4 + (d>>5)] = sq; }
    __syncthreads();
    float ts = red[0]+red[1]+red[2]+red[3];
    float tq = red[4]+red[5]+red[6]+red[7];
    float mean = ts * (1.0f/DKD);
    float var  = tq * (1.0f/DKD) - mean*mean;
    float inv  = rsqrtf(var + 1e-5f);
    g_h[(size_t)bx*DKD + d] = (v - mean)*inv*g0[d] + b0[d];
}

// ---------------- sincos precompute ------------------------------------------
__global__ void k_cs(const float* __restrict__ phi)
{
    int i = blockIdx.x*blockDim.x + threadIdx.x;
    if (i < LHN*PP) {
        float s, c;
        sincosf(phi[i], &s, &c);
        g_cosv[i] = c; g_sinv[i] = s;
    }
}

// ---------------- convert Vw (hi only) ----------------------------------------
__global__ void k_cvtVw(const float* __restrict__ Vw)
{
    int i = blockIdx.x*blockDim.x + threadIdx.x;
    if (i < LHN*DKD*DKD) g_Vwhi[i] = __float2half_rn(Vw[i]);
}

// ---------------- W build: brick-wall Givens pyramid -> transposed hi ---------
__global__ __launch_bounds__(256) void k_wbuild()
{
    int lh = blockIdx.x, cg = blockIdx.y;      // 48 x 4
    __shared__ float Wsh[SS][33];
    int tid = threadIdx.x;
    int col = tid & 31, slot = tid >> 5;
    for (int idx = tid; idx < SS*32; idx += 256) {
        int r = idx >> 5, c = idx & 31;
        Wsh[r][c] = (r == cg*32 + c) ? 1.0f : 0.0f;
    }
    __syncthreads();
    const float* cb = g_cosv + lh*PP;
    const float* sb = g_sinv + lh*PP;
    for (int t = 0; t <= 2*(SS-2); t++) {
        int par  = t & 1;
        int imax = min(t, 2*(SS-2) - t);
        int cnt  = ((imax - par) >> 1) + 1;
        for (int r = slot; r < cnt; r += 8) {
            int i = par + 2*r;
            int k = (t + i) >> 1;
            int p = ((k*(k+1)) >> 1) + k - i;
            float c = cb[p], s = sb[p];
            float ra = Wsh[i][col], rb = Wsh[i+1][col];
            Wsh[i][col]   = c*ra - s*rb;
            Wsh[i+1][col] = s*ra + c*rb;
        }
        __syncthreads();
    }
    for (int idx = tid; idx < 32*SS; idx += 256) {
        int r = idx & 127, c = idx >> 7;
        size_t o = (size_t)lh*DKD*DKD + (size_t)(cg*32 + c)*DKD + r;
        g_Wthi[o] = __float2half_rn(Wsh[r][c]);
    }
}

// ---------------- token norms + u hi (layer-0 prep) ---------------------------
__global__ void k_norm()
{
    int row = blockIdx.x;
    int d = threadIdx.x;
    float v = g_h[(size_t)row*DKD + d];
    float sq = v*v;
#pragma unroll
    for (int o = 16; o; o >>= 1) sq += __shfl_xor_sync(0xffffffffu, sq, o);
    __shared__ float red[4];
    if ((d & 31) == 0) red[d>>5] = sq;
    __syncthreads();
    float nrm = sqrtf(red[0]+red[1]+red[2]+red[3]);
    size_t o = (size_t)row*DKD + d;
    g_uhi[o] = __float2half_rn(v / nrm);
    if (d == 0) g_nrm[row] = nrm;
}

// ---------------- merge heads + norms + u hi (between layers) -----------------
__global__ void k_mergenorm(const float* __restrict__ mb, int l)
{
    int row = blockIdx.x;
    int d = threadIdx.x;
    size_t o = (size_t)row*DKD + d;
    float a = mb[l];
#pragma unroll
    for (int h = 0; h < HH; h++) a += g_hs[(size_t)h*BSD + o];
    float sq = a*a;
#pragma unroll
    for (int of = 16; of; of >>= 1) sq += __shfl_xor_sync(0xffffffffu, sq, of);
    __shared__ float red[4];
    if ((d & 31) == 0) red[d>>5] = sq;
    __syncthreads();
    float nrm = sqrtf(red[0]+red[1]+red[2]+red[3]);
    g_h[o] = a;
    g_uhi[o] = __float2half_rn(a / nrm);
    if (d == 0) g_nrm[row] = nrm;
}

// ---------------- fused layer kernel (3 tiles -> 2 CTAs/SM) -------------------
#define TSTRIDE 136
#define TILE1   (128*TSTRIDE*2)        /* 34816 bytes, one fp16 tile */
#define RAO     0                      /* u (persistent)              */
#define RBO     TILE1                  /* T1 -> P                     */
#define RCO     (2*TILE1)              /* W -> Vw -> V^T              */
#define SMO_F   (3*TILE1)
#define SMEM_TOTAL (3*TILE1 + 6144)

__device__ __forceinline__ void load_hi_async(uint32_t dst,
    const fp16* __restrict__ hi, int tid)
{
#pragma unroll
    for (int it = 0; it < 4; it++) {
        int idx = it*256 + tid;
        int row = idx >> 3, chunk = idx & 7;
        CP16(dst + (row*TSTRIDE + chunk*16)*2, hi + row*DKD + chunk*16);
        CP16(dst + (row*TSTRIDE + chunk*16 + 8)*2, hi + row*DKD + chunk*16 + 8);
    }
}

// 1-term fp16 128x128x128 gemm (A hi, B hi)
__device__ __forceinline__ void gemm1t(uint32_t aBase, uint32_t bBase,
                                       float acc[4][4][4], int lane, int wm, int wn)
{
    uint32_t aoff[4], b4off[2];
#pragma unroll
    for (int mi = 0; mi < 4; mi++)
        aoff[mi] = aBase + ((wm*64 + mi*16 + (lane & 15))*TSTRIDE + (lane >> 4)*8) * 2;
#pragma unroll
    for (int njp = 0; njp < 2; njp++)
        b4off[njp] = bBase + ((wn*32 + njp*16 + ((lane>>4)*8) + (lane & 7))*TSTRIDE
                              + (((lane >> 3) & 1)*8)) * 2;
#pragma unroll
    for (int mi = 0; mi < 4; mi++)
#pragma unroll
        for (int nj = 0; nj < 4; nj++)
#pragma unroll
            for (int q = 0; q < 4; q++) acc[mi][nj][q] = 0.0f;

#pragma unroll 2
    for (int kk = 0; kk < 8; kk++) {
        uint32_t k2 = kk*32;
        uint32_t ah[4][4], bh[2][4];
#pragma unroll
        for (int mi = 0; mi < 4; mi++)
            ldmx4(ah[mi], aoff[mi] + k2);
#pragma unroll
        for (int njp = 0; njp < 2; njp++)
            ldmx4(bh[njp], b4off[njp] + k2);
#pragma unroll
        for (int mi = 0; mi < 4; mi++)
#pragma unroll
            for (int nj = 0; nj < 4; nj++)
                mma16816(acc[mi][nj], ah[mi], &bh[nj>>1][(nj&1)*2]);
    }
}

// accumulator fragments -> smem fp16 hi tile (row-major A layout)
__device__ __forceinline__ void fragToTile(char* sm, uint32_t rOff, float acc[4][4][4],
                                           int lane, int wm, int wn)
{
    int gid = lane >> 2, tig = lane & 3;
#pragma unroll
    for (int mi = 0; mi < 4; mi++) {
        int r0 = wm*64 + mi*16 + gid;
#pragma unroll
        for (int nj = 0; nj < 4; nj++) {
            int c0 = wn*32 + nj*8 + tig*2;
#pragma unroll
            for (int half = 0; half < 2; half++) {
                int r = r0 + half*8;
                *(uint32_t*)(sm + rOff + (r*TSTRIDE + c0)*2) =
                    pack2h(acc[mi][nj][half*2], acc[mi][nj][half*2+1]);
            }
        }
    }
}

__global__ void __launch_bounds__(256, 2) k_layer(int l,
    const float* __restrict__ Vb, const float* __restrict__ lng,
    const float* __restrict__ lnb, const float* __restrict__ mw)
{
    extern __shared__ char sm[];
    uint32_t smb = smem_u32(sm);

    int bx = blockIdx.x;                 // batch / m-tile
    int h  = blockIdx.y;
    int tid = threadIdx.x, lane = tid & 31, wid = tid >> 5;
    int wm = wid >> 2, wn = wid & 3;
    int gid = lane >> 2, tig = lane & 3;

    float* fnrm = (float*)(sm + SMO_F);
    float* fvb  = fnrm + 128;
    float* fg   = fnrm + 256;
    float* fb   = fnrm + 384;
    float* red1 = fnrm + 512;            // 512 floats
    float* red2 = fnrm + 1024;           // 512 floats

    size_t tokBase = (size_t)bx*128*DKD;
    size_t lhOff   = (size_t)(l*HH + h)*DKD*DKD;
    size_t hsBase  = (size_t)h*BSD + tokBase;

    // group0: u -> RA, W -> RC
    load_hi_async(smb + RAO, g_uhi + tokBase, tid);
    load_hi_async(smb + RCO, g_Wthi + lhOff, tid);
    CP_COMMIT();
    if (tid < 128) {
        fnrm[tid] = g_nrm[bx*128 + tid];
        fvb[tid]  = Vb[(l*HH+h)*DKD + tid];
        fg[tid]   = lng[(size_t)(l*HH+h)*DKD + tid];
        fb[tid]   = lnb[(size_t)(l*HH+h)*DKD + tid];
    }
    CP_WAIT0();
    __syncthreads();                       // S1

    float acc[4][4][4];

    // GEMM1: T1 = u @ W
    gemm1t(smb + RAO, smb + RCO, acc, lane, wm, wn);
    fragToTile(sm, RBO, acc, lane, wm, wn);
    __syncthreads();                       // S2: T1 visible; RC free

    // Vw streams in under GEMM2
    load_hi_async(smb + RCO, g_Vwhi + lhOff, tid);
    CP_COMMIT();

    // GEMM2: M = T1 @ u^T
    gemm1t(smb + RBO, smb + RAO, acc, lane, wm, wn);
    CP_WAIT0();
    __syncthreads();                       // S3: RB free; Vw visible

    // ---- register softmax (A = M^2*n*n*scale >= 0, no max pass) ----
    {
        const float scale = 0.08838834764831845f;    // 1/sqrt(128)
        float nc[8];
#pragma unroll
        for (int nj = 0; nj < 4; nj++) {
            int c0 = wn*32 + nj*8 + tig*2;
            nc[2*nj]   = fnrm[c0];
            nc[2*nj+1] = fnrm[c0+1];
        }
#pragma unroll
        for (int mi = 0; mi < 4; mi++)
#pragma unroll
        for (int half = 0; half < 2; half++) {
            int r = wm*64 + mi*16 + half*8 + gid;
            float nr = fnrm[r] * scale;
            float s = 0.0f;
#pragma unroll
            for (int nj = 0; nj < 4; nj++) {
                float m0 = acc[mi][nj][half*2], m1 = acc[mi][nj][half*2+1];
                float e0 = __expf(m0*m0 * nr * nc[2*nj]);
                float e1 = __expf(m1*m1 * nr * nc[2*nj+1]);
                acc[mi][nj][half*2]   = e0;
                acc[mi][nj][half*2+1] = e1;
                s += e0 + e1;
            }
            s += __shfl_xor_sync(0xffffffffu, s, 1);
            s += __shfl_xor_sync(0xffffffffu, s, 2);
            if (tig == 0) red1[r*4 + wn] = s;
        }
        __syncthreads();                   // S4: row partial sums
#pragma unroll
        for (int mi = 0; mi < 4; mi++)
#pragma unroll
        for (int half = 0; half < 2; half++) {
            int r = wm*64 + mi*16 + half*8 + gid;
            float inv = 1.0f / (red1[r*4] + red1[r*4+1] + red1[r*4+2] + red1[r*4+3]);
#pragma unroll
            for (int nj = 0; nj < 4; nj++) {
                int c0 = wn*32 + nj*8 + tig*2;
                *(uint32_t*)(sm + RBO + (r*TSTRIDE + c0)*2) =
                    pack2h(acc[mi][nj][half*2]*inv, acc[mi][nj][half*2+1]*inv);
            }
        }
    }

    // GEMM3: V' = u @ Vw^T   (P store above needs no sync before this: reads RA/RC)
    gemm1t(smb + RAO, smb + RCO, acc, lane, wm, wn);
    __syncthreads();                       // S5: P visible; all warps done reading RC

    // V^T -> RC, scale by nrm, add bias
#pragma unroll
    for (int mi = 0; mi < 4; mi++) {
        int s0 = wm*64 + mi*16 + gid;
#pragma unroll
        for (int nj = 0; nj < 4; nj++) {
            int e0 = wn*32 + nj*8 + tig*2;
            float vb0 = fvb[e0], vb1 = fvb[e0+1];
#pragma unroll
            for (int half = 0; half < 2; half++) {
                int ss = s0 + half*8;
                float ns = fnrm[ss];
                *(fp16*)(sm + RCO + (e0*TSTRIDE + ss)*2)     = __float2half_rn(acc[mi][nj][half*2]*ns   + vb0);
                *(fp16*)(sm + RCO + ((e0+1)*TSTRIDE + ss)*2) = __float2half_rn(acc[mi][nj][half*2+1]*ns + vb1);
            }
        }
    }
    __syncthreads();                       // S6: V^T staged

    // GEMM4: O = P @ V^T
    gemm1t(smb + RBO, smb + RCO, acc, lane, wm, wn);

    // ---- register epilogue: +residual, LN (E[x^2]-m^2), *mw -> g_hs ----
    {
        float mwv = __ldg(mw + l*HH + h);
#pragma unroll
        for (int mi = 0; mi < 4; mi++)
#pragma unroll
        for (int half = 0; half < 2; half++) {
            int r = wm*64 + mi*16 + half*8 + gid;
            const float* hr = g_h + tokBase + (size_t)r*DKD;
            float s = 0.0f, s2 = 0.0f;
#pragma unroll
            for (int nj = 0; nj < 4; nj++) {
                int c0 = wn*32 + nj*8 + tig*2;
                float2 rv = *(const float2*)(hr + c0);
                float v0 = acc[mi][nj][half*2]   + rv.x;
                float v1 = acc[mi][nj][half*2+1] + rv.y;
                acc[mi][nj][half*2]   = v0;
                acc[mi][nj][half*2+1] = v1;
                s  += v0 + v1;
                s2 += v0*v0 + v1*v1;
            }
            s  += __shfl_xor_sync(0xffffffffu, s, 1);
            s  += __shfl_xor_sync(0xffffffffu, s, 2);
            s2 += __shfl_xor_sync(0xffffffffu, s2, 1);
            s2 += __shfl_xor_sync(0xffffffffu, s2, 2);
            if (tig == 0) { red1[r*4 + wn] = s; red2[r*4 + wn] = s2; }
        }
        __syncthreads();                   // S7
#pragma unroll
        for (int mi = 0; mi < 4; mi++)
#pragma unroll
        for (int half = 0; half < 2; half++) {
            int r = wm*64 + mi*16 + half*8 + gid;
            float s  = red1[r*4] + red1[r*4+1] + red1[r*4+2] + red1[r*4+3];
            float s2 = red2[r*4] + red2[r*4+1] + red2[r*4+2] + red2[r*4+3];
            float mean = s * (1.0f/DKD);
            float var  = s2 * (1.0f/DKD) - mean*mean;
            float inv  = rsqrtf(var + 1e-5f);
            float* op = g_hs + hsBase + (size_t)r*DKD;
#pragma unroll
            for (int nj = 0; nj < 4; nj++) {
                int c0 = wn*32 + nj*8 + tig*2;
                float2 o;
                o.x = ((acc[mi][nj][half*2]  -mean)*inv*fg[c0]   + fb[c0]  ) * mwv;
                o.y = ((acc[mi][nj][half*2+1]-mean)*inv*fg[c0+1] + fb[c0+1]) * mwv;
                *(float2*)(op + c0) = o;
            }
        }
    }
}

// ---------------- extract last token ------------------------------------------
__global__ void k_extract(float* __restrict__ out)
{
    int i = blockIdx.x*blockDim.x + threadIdx.x;
    if (i < BATCH*DKD) {
        int b = i >> 7, d = i & 127;
        out[i] = g_h[((size_t)b*SS + (SS-1))*DKD + d];
    }
}

// ---------------- launch ------------------------------------------------------
extern "C" void kernel_launch(void* const* d_in, const int* in_sizes, int n_in,
                              void* d_out, int out_size)
{
    const float* x        = (const float*)d_in[0];
    const float* embed_w  = (const float*)d_in[1];
    const float* embed_b  = (const float*)d_in[2];
    const float* class_tk = (const float*)d_in[3];
    const float* norm0_g  = (const float*)d_in[4];
    const float* norm0_b  = (const float*)d_in[5];
    const float* Vw       = (const float*)d_in[6];
    const float* Vb       = (const float*)d_in[7];
    const float* ln_g     = (const float*)d_in[8];
    const float* ln_b     = (const float*)d_in[9];
    const float* phi      = (const float*)d_in[10];
    const float* merger_w = (const float*)d_in[11];
    const float* merger_b = (const float*)d_in[12];
    float* out = (float*)d_out;

    static int smem_set = 0;
    if (!smem_set) {
        cudaFuncSetAttribute(k_layer, cudaFuncAttributeMaxDynamicSharedMemorySize, SMEM_TOTAL);
        smem_set = 1;
    }

    k_embed<<<BS, 128>>>(x, embed_w, embed_b, class_tk, norm0_g, norm0_b);
    k_cs<<<(LHN*PP + 255)/256, 256>>>(phi);
    k_wbuild<<<dim3(LHN, 4), 256>>>();
    k_cvtVw<<<(LHN*DKD*DKD + 255)/256, 256>>>(Vw);
    k_norm<<<BS, 128>>>();

    dim3 gg(BATCH, HH);
    for (int l = 0; l < LL; l++) {
        k_layer<<<gg, 256, SMEM_TOTAL>>>(l, Vb, ln_g, ln_b, merger_w);
        k_mergenorm<<<BS, 128>>>(merger_b, l);
    }
    k_extract<<<(BATCH*DKD + 255)/256, 256>>>(out);
}